// round 4
// baseline (speedup 1.0000x reference)
#include <cuda_runtime.h>
#include <math_constants.h>

#define S_LEN 2048
#define BATCH 4
#define EMB   1024
#define HEADS 16
#define HD    64
#define E3    3072
#define MROWS (S_LEN * BATCH)   // 8192

// Scratch (allocation-free rule: __device__ globals)
__device__ float g_lin[S_LEN * BATCH * E3];   // in_proj output [S,B,3E]
__device__ float g_ctx[S_LEN * BATCH * EMB];  // attention context [S,B,E]

// ---------------------------------------------------------------------------
// C[M,N] = A[M,K] * B[N,K]^T + bias[N]     (A, B row-major; K % 16 == 0)
// 128x128 tile, K-step 16, 256 threads, 8x8 per thread, double-buffered smem.
// Each thread prefetches 2 independent float4s per matrix per step (MLP=2).
// ---------------------------------------------------------------------------
__global__ __launch_bounds__(256) void sgemm_nt_bias(
    const float* __restrict__ A, const float* __restrict__ Bm,
    const float* __restrict__ bias, float* __restrict__ C,
    int M, int N, int K)
{
    __shared__ float As[2][16][128];
    __shared__ float Bs[2][16][128];

    const int tid = threadIdx.x;
    const int tr  = tid >> 4;        // 0..15  (M sub-tile)
    const int tc  = tid & 15;        // 0..15  (N sub-tile)

    const int lrow = tid >> 1;             // 0..127
    const int lq0  = (tid & 1) << 3;       // 0 or 8  (two quads: lq0, lq0+4)

    const float* Ab = A  + (size_t)(blockIdx.y * 128 + lrow) * K + lq0;
    const float* Bb = Bm + (size_t)(blockIdx.x * 128 + lrow) * K + lq0;

    float acc[8][8];
#pragma unroll
    for (int i = 0; i < 8; i++)
#pragma unroll
        for (int j = 0; j < 8; j++) acc[i][j] = 0.f;

    // Prologue: fill buffer 0
    {
        float4 a0 = *(const float4*)(Ab);
        float4 a1 = *(const float4*)(Ab + 4);
        float4 b0 = *(const float4*)(Bb);
        float4 b1 = *(const float4*)(Bb + 4);
        As[0][lq0 + 0][lrow] = a0.x; As[0][lq0 + 1][lrow] = a0.y;
        As[0][lq0 + 2][lrow] = a0.z; As[0][lq0 + 3][lrow] = a0.w;
        As[0][lq0 + 4][lrow] = a1.x; As[0][lq0 + 5][lrow] = a1.y;
        As[0][lq0 + 6][lrow] = a1.z; As[0][lq0 + 7][lrow] = a1.w;
        Bs[0][lq0 + 0][lrow] = b0.x; Bs[0][lq0 + 1][lrow] = b0.y;
        Bs[0][lq0 + 2][lrow] = b0.z; Bs[0][lq0 + 3][lrow] = b0.w;
        Bs[0][lq0 + 4][lrow] = b1.x; Bs[0][lq0 + 5][lrow] = b1.y;
        Bs[0][lq0 + 6][lrow] = b1.z; Bs[0][lq0 + 7][lrow] = b1.w;
    }
    __syncthreads();

    int buf = 0;
    for (int k0 = 16; k0 < K; k0 += 16) {
        // Prefetch next K-step (2 independent LDG.128 per matrix)
        float4 a0 = *(const float4*)(Ab + k0);
        float4 a1 = *(const float4*)(Ab + k0 + 4);
        float4 b0 = *(const float4*)(Bb + k0);
        float4 b1 = *(const float4*)(Bb + k0 + 4);

#pragma unroll
        for (int kk = 0; kk < 16; kk++) {
            float4 x0 = *(const float4*)&As[buf][kk][tr * 8];
            float4 x1 = *(const float4*)&As[buf][kk][tr * 8 + 4];
            float4 y0 = *(const float4*)&Bs[buf][kk][tc * 8];
            float4 y1 = *(const float4*)&Bs[buf][kk][tc * 8 + 4];
            float ar[8] = {x0.x, x0.y, x0.z, x0.w, x1.x, x1.y, x1.z, x1.w};
            float br[8] = {y0.x, y0.y, y0.z, y0.w, y1.x, y1.y, y1.z, y1.w};
#pragma unroll
            for (int i = 0; i < 8; i++)
#pragma unroll
                for (int j = 0; j < 8; j++)
                    acc[i][j] = fmaf(ar[i], br[j], acc[i][j]);
        }

        const int nb = buf ^ 1;
        As[nb][lq0 + 0][lrow] = a0.x; As[nb][lq0 + 1][lrow] = a0.y;
        As[nb][lq0 + 2][lrow] = a0.z; As[nb][lq0 + 3][lrow] = a0.w;
        As[nb][lq0 + 4][lrow] = a1.x; As[nb][lq0 + 5][lrow] = a1.y;
        As[nb][lq0 + 6][lrow] = a1.z; As[nb][lq0 + 7][lrow] = a1.w;
        Bs[nb][lq0 + 0][lrow] = b0.x; Bs[nb][lq0 + 1][lrow] = b0.y;
        Bs[nb][lq0 + 2][lrow] = b0.z; Bs[nb][lq0 + 3][lrow] = b0.w;
        Bs[nb][lq0 + 4][lrow] = b1.x; Bs[nb][lq0 + 5][lrow] = b1.y;
        Bs[nb][lq0 + 6][lrow] = b1.z; Bs[nb][lq0 + 7][lrow] = b1.w;
        __syncthreads();
        buf = nb;
    }

    // Epilogue compute on last buffer
#pragma unroll
    for (int kk = 0; kk < 16; kk++) {
        float4 x0 = *(const float4*)&As[buf][kk][tr * 8];
        float4 x1 = *(const float4*)&As[buf][kk][tr * 8 + 4];
        float4 y0 = *(const float4*)&Bs[buf][kk][tc * 8];
        float4 y1 = *(const float4*)&Bs[buf][kk][tc * 8 + 4];
        float ar[8] = {x0.x, x0.y, x0.z, x0.w, x1.x, x1.y, x1.z, x1.w};
        float br[8] = {y0.x, y0.y, y0.z, y0.w, y1.x, y1.y, y1.z, y1.w};
#pragma unroll
        for (int i = 0; i < 8; i++)
#pragma unroll
            for (int j = 0; j < 8; j++)
                acc[i][j] = fmaf(ar[i], br[j], acc[i][j]);
    }

    const int row0 = blockIdx.y * 128 + tr * 8;
    const int col0 = blockIdx.x * 128 + tc * 8;
    float bb[8];
#pragma unroll
    for (int j = 0; j < 8; j++) bb[j] = bias[col0 + j];
#pragma unroll
    for (int i = 0; i < 8; i++) {
        float4 r0 = make_float4(acc[i][0] + bb[0], acc[i][1] + bb[1],
                                acc[i][2] + bb[2], acc[i][3] + bb[3]);
        float4 r1 = make_float4(acc[i][4] + bb[4], acc[i][5] + bb[5],
                                acc[i][6] + bb[6], acc[i][7] + bb[7]);
        *(float4*)&C[(size_t)(row0 + i) * N + col0]     = r0;
        *(float4*)&C[(size_t)(row0 + i) * N + col0 + 4] = r1;
    }
}

// ---------------------------------------------------------------------------
// Flash attention, fp32. One block = 128 q-rows (2 sub-tiles of 64) of one
// (b,h): K/V tile loads are shared by both sub-tiles (halves K/V L2 traffic).
// grid = (S/128, B*H); 256 threads (16x16); per sub-tile each thread owns
// 4 q-rows x 4 cols.
// lin layout: lin[((s)*B + b)*3072 + h*192 + c*64 + d], c = 0:q 1:k 2:v
// ---------------------------------------------------------------------------
#define AT_STRIDE 68   // 64 + 4 pad, keeps float4 alignment, breaks bank cycles

extern __shared__ float at_smem[];

__global__ __launch_bounds__(256) void attn_kernel()
{
    float* Qs = at_smem;                       // [2][64][68], pre-scaled
    float* Kt = Qs + 2 * 64 * AT_STRIDE;       // [d=64][c=64(+4)] transposed K
    float* Vs = Kt + 64 * AT_STRIDE;           // [t=64][d=64(+4)]
    float* Ps = Vs + 64 * AT_STRIDE;           // [2][64][68]

    const int tid = threadIdx.x;
    const int tx  = tid & 15;          // col group
    const int ty  = tid >> 4;          // row group
    const int ty4 = ty * 4;
    const int qt  = blockIdx.x;        // 128-row q tile
    const int bh  = blockIdx.y;
    const int b   = bh >> 4;
    const int h   = bh & 15;
    const float scale = 0.125f;        // hd^-0.5

    const size_t base = (size_t)b * E3 + (size_t)h * (3 * HD);
    const size_t srow = (size_t)BATCH * E3;   // stride over s/t in g_lin

    // Load both Q sub-tiles (pre-scaled): 2048 float4s over 256 threads
#pragma unroll
    for (int it = 0; it < 8; it++) {
        int qi = tid + it * 256;               // 0..2047
        int r  = qi >> 4;                      // 0..127
        int dq = (qi & 15) << 2;               // 0..60
        float4 q4 = *(const float4*)&g_lin[(size_t)(qt * 128 + r) * srow + base + dq];
        float* dst = &Qs[r * AT_STRIDE + dq];  // [2][64] flattened as r=0..127
        dst[0] = q4.x * scale; dst[1] = q4.y * scale;
        dst[2] = q4.z * scale; dst[3] = q4.w * scale;
    }

    float m[2][4], l[2][4];
    float4 o[2][4];
#pragma unroll
    for (int u = 0; u < 2; u++)
#pragma unroll
        for (int i = 0; i < 4; i++) {
            m[u][i] = -CUDART_INF_F; l[u][i] = 0.f;
            o[u][i] = make_float4(0.f, 0.f, 0.f, 0.f);
        }

    for (int kt = 0; kt < S_LEN / 64; kt++) {
        __syncthreads();   // protect Kt/Vs/Ps from previous iteration readers
        // Load K (transposed) and V tiles — shared by both q sub-tiles
#pragma unroll
        for (int it = 0; it < 4; it++) {
            int qi = tid + it * 256;
            int c  = qi >> 4;              // key/value row in tile
            int dq = (qi & 15) << 2;
            size_t g = (size_t)(kt * 64 + c) * srow + base;
            float4 k4 = *(const float4*)&g_lin[g + HD + dq];
            float4 v4 = *(const float4*)&g_lin[g + 2 * HD + dq];
            Kt[(dq + 0) * AT_STRIDE + c] = k4.x;
            Kt[(dq + 1) * AT_STRIDE + c] = k4.y;
            Kt[(dq + 2) * AT_STRIDE + c] = k4.z;
            Kt[(dq + 3) * AT_STRIDE + c] = k4.w;
            *(float4*)&Vs[c * AT_STRIDE + dq] = v4;
        }
        __syncthreads();

#pragma unroll
        for (int u = 0; u < 2; u++) {
            const float* Qu = Qs + u * 64 * AT_STRIDE;
            float*       Pu = Ps + u * 64 * AT_STRIDE;

            // S = Q * K^T  (4x4 per thread)
            float s[4][4];
#pragma unroll
            for (int i = 0; i < 4; i++)
#pragma unroll
                for (int j = 0; j < 4; j++) s[i][j] = 0.f;

#pragma unroll 4
            for (int d = 0; d < 64; d += 4) {
                float4 k0 = *(const float4*)&Kt[(d + 0) * AT_STRIDE + tx * 4];
                float4 k1 = *(const float4*)&Kt[(d + 1) * AT_STRIDE + tx * 4];
                float4 k2 = *(const float4*)&Kt[(d + 2) * AT_STRIDE + tx * 4];
                float4 k3 = *(const float4*)&Kt[(d + 3) * AT_STRIDE + tx * 4];
#pragma unroll
                for (int i = 0; i < 4; i++) {
                    float4 q = *(const float4*)&Qu[(ty4 + i) * AT_STRIDE + d];
                    s[i][0] += q.x * k0.x + q.y * k1.x + q.z * k2.x + q.w * k3.x;
                    s[i][1] += q.x * k0.y + q.y * k1.y + q.z * k2.y + q.w * k3.y;
                    s[i][2] += q.x * k0.z + q.y * k1.z + q.z * k2.z + q.w * k3.z;
                    s[i][3] += q.x * k0.w + q.y * k1.w + q.z * k2.w + q.w * k3.w;
                }
            }

            // Online softmax
#pragma unroll
            for (int i = 0; i < 4; i++) {
                float tmax = fmaxf(fmaxf(s[i][0], s[i][1]), fmaxf(s[i][2], s[i][3]));
#pragma unroll
                for (int off = 1; off <= 8; off <<= 1)
                    tmax = fmaxf(tmax, __shfl_xor_sync(0xffffffffu, tmax, off));
                float mnew = fmaxf(m[u][i], tmax);
                float corr = __expf(m[u][i] - mnew);
                m[u][i] = mnew;
                l[u][i] *= corr;
                o[u][i].x *= corr; o[u][i].y *= corr;
                o[u][i].z *= corr; o[u][i].w *= corr;

                float p0 = __expf(s[i][0] - mnew);
                float p1 = __expf(s[i][1] - mnew);
                float p2 = __expf(s[i][2] - mnew);
                float p3 = __expf(s[i][3] - mnew);
                float psum = p0 + p1 + p2 + p3;
#pragma unroll
                for (int off = 1; off <= 8; off <<= 1)
                    psum += __shfl_xor_sync(0xffffffffu, psum, off);
                l[u][i] += psum;
                *(float4*)&Pu[(ty4 + i) * AT_STRIDE + tx * 4] =
                    make_float4(p0, p1, p2, p3);
            }
        }
        __syncthreads();   // Ps written by all threads before PV reads

        // O += P * V for both sub-tiles
#pragma unroll 4
        for (int j = 0; j < 64; j += 4) {
            float4 v0 = *(const float4*)&Vs[(j + 0) * AT_STRIDE + tx * 4];
            float4 v1 = *(const float4*)&Vs[(j + 1) * AT_STRIDE + tx * 4];
            float4 v2 = *(const float4*)&Vs[(j + 2) * AT_STRIDE + tx * 4];
            float4 v3 = *(const float4*)&Vs[(j + 3) * AT_STRIDE + tx * 4];
#pragma unroll
            for (int u = 0; u < 2; u++) {
                const float* Pu = Ps + u * 64 * AT_STRIDE;
#pragma unroll
                for (int i = 0; i < 4; i++) {
                    float4 p = *(const float4*)&Pu[(ty4 + i) * AT_STRIDE + j];
                    o[u][i].x += p.x * v0.x + p.y * v1.x + p.z * v2.x + p.w * v3.x;
                    o[u][i].y += p.x * v0.y + p.y * v1.y + p.z * v2.y + p.w * v3.y;
                    o[u][i].z += p.x * v0.z + p.y * v1.z + p.z * v2.z + p.w * v3.z;
                    o[u][i].w += p.x * v0.w + p.y * v1.w + p.z * v2.w + p.w * v3.w;
                }
            }
        }
    }

    // Normalize and write ctx[s, b, h*64 + d]
#pragma unroll
    for (int u = 0; u < 2; u++)
#pragma unroll
        for (int i = 0; i < 4; i++) {
            float inv = 1.f / l[u][i];
            float4 r = make_float4(o[u][i].x * inv, o[u][i].y * inv,
                                   o[u][i].z * inv, o[u][i].w * inv);
            int srow_i = qt * 128 + u * 64 + ty4 + i;
            *(float4*)&g_ctx[((size_t)srow_i * BATCH + b) * EMB + h * HD + tx * 4] = r;
        }
}

// ---------------------------------------------------------------------------
extern "C" void kernel_launch(void* const* d_in, const int* in_sizes, int n_in,
                              void* d_out, int out_size)
{
    const float* query = (const float*)d_in[0];
    const float* w_in  = (const float*)d_in[1];
    const float* b_in  = (const float*)d_in[2];
    const float* w_out = (const float*)d_in[3];
    const float* b_out = (const float*)d_in[4];
    float* out = (float*)d_out;

    float *lin_ptr, *ctx_ptr;
    cudaGetSymbolAddress((void**)&lin_ptr, g_lin);
    cudaGetSymbolAddress((void**)&ctx_ptr, g_ctx);

    const int smem = 6 * 64 * AT_STRIDE * (int)sizeof(float); // 104448 B
    cudaFuncSetAttribute(attn_kernel,
                         cudaFuncAttributeMaxDynamicSharedMemorySize, smem);

    // 1) lin = query @ W_in^T + b_in   [8192 x 3072]
    sgemm_nt_bias<<<dim3(E3 / 128, MROWS / 128), 256>>>(
        query, w_in, b_in, lin_ptr, MROWS, E3, EMB);

    // 2) flash attention -> g_ctx  (128 q-rows per block)
    attn_kernel<<<dim3(S_LEN / 128, BATCH * HEADS), 256, smem>>>();

    // 3) out = ctx @ W_out^T + b_out   [8192 x 1024]
    sgemm_nt_bias<<<dim3(EMB / 128, MROWS / 128), 256>>>(
        ctx_ptr, w_out, b_out, out, MROWS, EMB, EMB);
}

// round 15
// speedup vs baseline: 2.8645x; 2.8645x over previous
#include <cuda_runtime.h>
#include <math_constants.h>

#define S_LEN 2048
#define BATCH 4
#define EMB   1024
#define HEADS 16
#define HD    64
#define E3    3072
#define MROWS (S_LEN * BATCH)   // 8192

// Scratch (allocation-free rule: __device__ globals)
__device__ float g_lin[S_LEN * BATCH * E3];   // in_proj output [S,B,3E]
__device__ float g_ctx[S_LEN * BATCH * EMB];  // attention context [S,B,E]

__device__ __forceinline__ unsigned cvt_tf32(float x) {
    unsigned r;
    asm("cvt.rna.tf32.f32 %0, %1;" : "=r"(r) : "f"(x));
    return r;
}

__device__ __forceinline__ void mma_tf32(float* c, const unsigned* a, const unsigned* b) {
    asm volatile(
        "mma.sync.aligned.m16n8k8.row.col.f32.tf32.tf32.f32 "
        "{%0,%1,%2,%3}, {%4,%5,%6,%7}, {%8,%9}, {%0,%1,%2,%3};"
        : "+f"(c[0]), "+f"(c[1]), "+f"(c[2]), "+f"(c[3])
        : "r"(a[0]), "r"(a[1]), "r"(a[2]), "r"(a[3]),
          "r"(b[0]), "r"(b[1]));
}

// ---------------------------------------------------------------------------
// TF32 tensor-core GEMM: C[M,N] = A[M,K] * B[N,K]^T + bias[N]
// 128x128 tile, BK=16 double-buffered, 256 threads (8 warps),
// warp tile 32x64, mma.m16n8k8.tf32, fp32 accumulate.
// smem k-major, stride 136 -> conflict-free fragment LDS.
// ---------------------------------------------------------------------------
#define AS_STR 136

__global__ __launch_bounds__(256) void gemm_tf32_nt_bias(
    const float* __restrict__ A, const float* __restrict__ Bm,
    const float* __restrict__ bias, float* __restrict__ C,
    int M, int N, int K)
{
    __shared__ unsigned As[2][16][AS_STR];
    __shared__ unsigned Bs[2][16][AS_STR];

    const int tid  = threadIdx.x;
    const int lane = tid & 31;
    const int warp = tid >> 5;
    const int wm   = (warp >> 1) << 5;   // 0,32,64,96
    const int wn   = (warp & 1) << 6;    // 0,64
    const int r    = lane >> 2;          // groupID 0..7
    const int cq   = lane & 3;           // threadID_in_group 0..3

    const int lrow = tid >> 1;           // 0..127
    const int lq0  = (tid & 1) << 3;     // 0 or 8

    const float* Ab = A  + (size_t)(blockIdx.y * 128 + lrow) * K + lq0;
    const float* Bb = Bm + (size_t)(blockIdx.x * 128 + lrow) * K + lq0;

    float c[2][8][4];
#pragma unroll
    for (int mt = 0; mt < 2; mt++)
#pragma unroll
        for (int nt = 0; nt < 8; nt++)
#pragma unroll
            for (int i = 0; i < 4; i++) c[mt][nt][i] = 0.f;

    {
        float4 a0 = *(const float4*)(Ab);
        float4 a1 = *(const float4*)(Ab + 4);
        float4 b0 = *(const float4*)(Bb);
        float4 b1 = *(const float4*)(Bb + 4);
        As[0][lq0 + 0][lrow] = cvt_tf32(a0.x); As[0][lq0 + 1][lrow] = cvt_tf32(a0.y);
        As[0][lq0 + 2][lrow] = cvt_tf32(a0.z); As[0][lq0 + 3][lrow] = cvt_tf32(a0.w);
        As[0][lq0 + 4][lrow] = cvt_tf32(a1.x); As[0][lq0 + 5][lrow] = cvt_tf32(a1.y);
        As[0][lq0 + 6][lrow] = cvt_tf32(a1.z); As[0][lq0 + 7][lrow] = cvt_tf32(a1.w);
        Bs[0][lq0 + 0][lrow] = cvt_tf32(b0.x); Bs[0][lq0 + 1][lrow] = cvt_tf32(b0.y);
        Bs[0][lq0 + 2][lrow] = cvt_tf32(b0.z); Bs[0][lq0 + 3][lrow] = cvt_tf32(b0.w);
        Bs[0][lq0 + 4][lrow] = cvt_tf32(b1.x); Bs[0][lq0 + 5][lrow] = cvt_tf32(b1.y);
        Bs[0][lq0 + 6][lrow] = cvt_tf32(b1.z); Bs[0][lq0 + 7][lrow] = cvt_tf32(b1.w);
    }
    __syncthreads();

    int buf = 0;
    for (int k0 = 16; k0 <= K; k0 += 16) {
        float4 a0, a1, b0, b1;
        const bool more = (k0 < K);
        if (more) {
            a0 = *(const float4*)(Ab + k0);
            a1 = *(const float4*)(Ab + k0 + 4);
            b0 = *(const float4*)(Bb + k0);
            b1 = *(const float4*)(Bb + k0 + 4);
        }

#pragma unroll
        for (int ks = 0; ks < 16; ks += 8) {
            unsigned af[2][4], bf[8][2];
#pragma unroll
            for (int mt = 0; mt < 2; mt++) {
                const int m0 = wm + mt * 16 + r;
                af[mt][0] = As[buf][ks + cq    ][m0];
                af[mt][1] = As[buf][ks + cq    ][m0 + 8];
                af[mt][2] = As[buf][ks + cq + 4][m0];
                af[mt][3] = As[buf][ks + cq + 4][m0 + 8];
            }
#pragma unroll
            for (int nt = 0; nt < 8; nt++) {
                const int n0 = wn + nt * 8 + r;
                bf[nt][0] = Bs[buf][ks + cq    ][n0];
                bf[nt][1] = Bs[buf][ks + cq + 4][n0];
            }
#pragma unroll
            for (int mt = 0; mt < 2; mt++)
#pragma unroll
                for (int nt = 0; nt < 8; nt++)
                    mma_tf32(c[mt][nt], af[mt], bf[nt]);
        }

        if (more) {
            const int nb = buf ^ 1;
            As[nb][lq0 + 0][lrow] = cvt_tf32(a0.x); As[nb][lq0 + 1][lrow] = cvt_tf32(a0.y);
            As[nb][lq0 + 2][lrow] = cvt_tf32(a0.z); As[nb][lq0 + 3][lrow] = cvt_tf32(a0.w);
            As[nb][lq0 + 4][lrow] = cvt_tf32(a1.x); As[nb][lq0 + 5][lrow] = cvt_tf32(a1.y);
            As[nb][lq0 + 6][lrow] = cvt_tf32(a1.z); As[nb][lq0 + 7][lrow] = cvt_tf32(a1.w);
            Bs[nb][lq0 + 0][lrow] = cvt_tf32(b0.x); Bs[nb][lq0 + 1][lrow] = cvt_tf32(b0.y);
            Bs[nb][lq0 + 2][lrow] = cvt_tf32(b0.z); Bs[nb][lq0 + 3][lrow] = cvt_tf32(b0.w);
            Bs[nb][lq0 + 4][lrow] = cvt_tf32(b1.x); Bs[nb][lq0 + 5][lrow] = cvt_tf32(b1.y);
            Bs[nb][lq0 + 6][lrow] = cvt_tf32(b1.z); Bs[nb][lq0 + 7][lrow] = cvt_tf32(b1.w);
            __syncthreads();
            buf = nb;
        }
    }

    const int brow = blockIdx.y * 128 + wm;
    const int bcol = blockIdx.x * 128 + wn;
#pragma unroll
    for (int nt = 0; nt < 8; nt++) {
        const int col = bcol + nt * 8 + 2 * cq;
        const float bb0 = bias[col];
        const float bb1 = bias[col + 1];
#pragma unroll
        for (int mt = 0; mt < 2; mt++) {
            const int row0 = brow + mt * 16 + r;
            float2 lo = make_float2(c[mt][nt][0] + bb0, c[mt][nt][1] + bb1);
            float2 hi = make_float2(c[mt][nt][2] + bb0, c[mt][nt][3] + bb1);
            *(float2*)&C[(size_t)row0 * N + col]       = lo;
            *(float2*)&C[(size_t)(row0 + 8) * N + col] = hi;
        }
    }
}

// ---------------------------------------------------------------------------
// Flash attention with tf32 MMA for QK^T and PV; fp32 online softmax.
// Block = 128 q-rows of one (b,h); 8 warps, warp tile m16 x n64.
// smem: Qs[128][68] Ks[64][68] Vs[64][72] Ps[128][68]  (tf32 words)
// K and V stay [t][d] row-major (row.col mma B-fragment reads them directly).
// P is warp-private: only __syncwarp between P store and PV fragment loads.
// lin layout: lin[((s)*B + b)*3072 + h*192 + c*64 + d], c = 0:q 1:k 2:v
// ---------------------------------------------------------------------------
#define QS_STR 68
#define KS_STR 68
#define VS_STR 72
#define PS_STR 68

extern __shared__ unsigned at_usmem[];

__global__ __launch_bounds__(256) void attn_mma_kernel()
{
    unsigned* Qs = at_usmem;                 // [128][68]
    unsigned* Ks = Qs + 128 * QS_STR;        // [64][68]
    unsigned* Vs = Ks + 64 * KS_STR;         // [64][72]
    unsigned* Ps = Vs + 64 * VS_STR;         // [128][68]

    const int tid  = threadIdx.x;
    const int lane = tid & 31;
    const int warp = tid >> 5;
    const int r    = lane >> 2;      // groupID 0..7
    const int cq   = lane & 3;       // threadID_in_group 0..3
    const int wq   = warp * 16;      // warp's q-row base in block

    const int qt = blockIdx.x;
    const int bh = blockIdx.y;
    const int b  = bh >> 4;
    const int h  = bh & 15;
    const float scale = 0.125f;      // hd^-0.5

    const size_t base = (size_t)b * E3 + (size_t)h * (3 * HD);
    const size_t srow = (size_t)BATCH * E3;

    // Load Q tile (scaled, tf32): 128 rows x 64 d
#pragma unroll
    for (int it = 0; it < 8; it++) {
        int qi = tid + it * 256;               // 0..2047 float4 slots
        int rr = qi >> 4;                      // 0..127
        int dq = (qi & 15) << 2;               // 0..60
        float4 q4 = *(const float4*)&g_lin[(size_t)(qt * 128 + rr) * srow + base + dq];
        unsigned* dst = &Qs[rr * QS_STR + dq];
        dst[0] = cvt_tf32(q4.x * scale); dst[1] = cvt_tf32(q4.y * scale);
        dst[2] = cvt_tf32(q4.z * scale); dst[3] = cvt_tf32(q4.w * scale);
    }

    float m[2] = {-CUDART_INF_F, -CUDART_INF_F};
    float l[2] = {0.f, 0.f};
    float co[8][4];
#pragma unroll
    for (int nt = 0; nt < 8; nt++)
#pragma unroll
        for (int i = 0; i < 4; i++) co[nt][i] = 0.f;

    for (int kt = 0; kt < S_LEN / 64; kt++) {
        __syncthreads();   // previous PV finished reading Vs / QK reading Ks
        // Load K,V chunk [64][64] each, tf32
#pragma unroll
        for (int it = 0; it < 4; it++) {
            int qi = tid + it * 256;           // 0..1023
            int t  = qi >> 4;                  // 0..63
            int dq = (qi & 15) << 2;
            size_t g = (size_t)(kt * 64 + t) * srow + base;
            float4 k4 = *(const float4*)&g_lin[g + HD + dq];
            float4 v4 = *(const float4*)&g_lin[g + 2 * HD + dq];
            unsigned* kd = &Ks[t * KS_STR + dq];
            kd[0] = cvt_tf32(k4.x); kd[1] = cvt_tf32(k4.y);
            kd[2] = cvt_tf32(k4.z); kd[3] = cvt_tf32(k4.w);
            unsigned* vd = &Vs[t * VS_STR + dq];
            vd[0] = cvt_tf32(v4.x); vd[1] = cvt_tf32(v4.y);
            vd[2] = cvt_tf32(v4.z); vd[3] = cvt_tf32(v4.w);
        }
        __syncthreads();

        // ---- S = Q K^T : warp computes 16 x 64, k = 64 ----
        float cs[8][4];
#pragma unroll
        for (int nt = 0; nt < 8; nt++)
#pragma unroll
            for (int i = 0; i < 4; i++) cs[nt][i] = 0.f;

#pragma unroll
        for (int ks = 0; ks < 64; ks += 8) {
            unsigned a[4];
            a[0] = Qs[(wq + r)     * QS_STR + ks + cq];
            a[1] = Qs[(wq + r + 8) * QS_STR + ks + cq];
            a[2] = Qs[(wq + r)     * QS_STR + ks + cq + 4];
            a[3] = Qs[(wq + r + 8) * QS_STR + ks + cq + 4];
#pragma unroll
            for (int nt = 0; nt < 8; nt++) {
                unsigned bfr[2];
                bfr[0] = Ks[(nt * 8 + r) * KS_STR + ks + cq];
                bfr[1] = Ks[(nt * 8 + r) * KS_STR + ks + cq + 4];
                mma_tf32(cs[nt], a, bfr);
            }
        }

        // ---- online softmax (rows wq+r and wq+r+8) ----
        float mx0 = -CUDART_INF_F, mx1 = -CUDART_INF_F;
#pragma unroll
        for (int nt = 0; nt < 8; nt++) {
            mx0 = fmaxf(mx0, fmaxf(cs[nt][0], cs[nt][1]));
            mx1 = fmaxf(mx1, fmaxf(cs[nt][2], cs[nt][3]));
        }
#pragma unroll
        for (int off = 1; off <= 2; off <<= 1) {
            mx0 = fmaxf(mx0, __shfl_xor_sync(0xffffffffu, mx0, off));
            mx1 = fmaxf(mx1, __shfl_xor_sync(0xffffffffu, mx1, off));
        }
        float mn0 = fmaxf(m[0], mx0);
        float mn1 = fmaxf(m[1], mx1);
        float cr0 = __expf(m[0] - mn0);
        float cr1 = __expf(m[1] - mn1);
        m[0] = mn0; m[1] = mn1;
        l[0] *= cr0; l[1] *= cr1;
#pragma unroll
        for (int nt = 0; nt < 8; nt++) {
            co[nt][0] *= cr0; co[nt][1] *= cr0;
            co[nt][2] *= cr1; co[nt][3] *= cr1;
        }

        float sum0 = 0.f, sum1 = 0.f;
#pragma unroll
        for (int nt = 0; nt < 8; nt++) {
            float p0 = __expf(cs[nt][0] - mn0);
            float p1 = __expf(cs[nt][1] - mn0);
            float p2 = __expf(cs[nt][2] - mn1);
            float p3 = __expf(cs[nt][3] - mn1);
            sum0 += p0 + p1;
            sum1 += p2 + p3;
            uint2 w0; w0.x = cvt_tf32(p0); w0.y = cvt_tf32(p1);
            uint2 w1; w1.x = cvt_tf32(p2); w1.y = cvt_tf32(p3);
            *(uint2*)&Ps[(wq + r)     * PS_STR + nt * 8 + 2 * cq] = w0;
            *(uint2*)&Ps[(wq + r + 8) * PS_STR + nt * 8 + 2 * cq] = w1;
        }
#pragma unroll
        for (int off = 1; off <= 2; off <<= 1) {
            sum0 += __shfl_xor_sync(0xffffffffu, sum0, off);
            sum1 += __shfl_xor_sync(0xffffffffu, sum1, off);
        }
        l[0] += sum0; l[1] += sum1;

        __syncwarp();   // P stores visible to whole warp before fragment loads

        // ---- O += P V : warp computes 16 x 64, k = 64 ----
#pragma unroll
        for (int ks = 0; ks < 64; ks += 8) {
            unsigned a[4];
            a[0] = Ps[(wq + r)     * PS_STR + ks + cq];
            a[1] = Ps[(wq + r + 8) * PS_STR + ks + cq];
            a[2] = Ps[(wq + r)     * PS_STR + ks + cq + 4];
            a[3] = Ps[(wq + r + 8) * PS_STR + ks + cq + 4];
#pragma unroll
            for (int nt = 0; nt < 8; nt++) {
                unsigned bfr[2];
                bfr[0] = Vs[(ks + cq)     * VS_STR + nt * 8 + r];
                bfr[1] = Vs[(ks + cq + 4) * VS_STR + nt * 8 + r];
                mma_tf32(co[nt], a, bfr);
            }
        }
    }

    // Normalize, write ctx[s, b, h*64 + d]
    const float inv0 = 1.f / l[0];
    const float inv1 = 1.f / l[1];
    const int row0 = qt * 128 + wq + r;
#pragma unroll
    for (int nt = 0; nt < 8; nt++) {
        const int col = h * HD + nt * 8 + 2 * cq;
        float2 lo = make_float2(co[nt][0] * inv0, co[nt][1] * inv0);
        float2 hi = make_float2(co[nt][2] * inv1, co[nt][3] * inv1);
        *(float2*)&g_ctx[((size_t)row0 * BATCH + b) * EMB + col]       = lo;
        *(float2*)&g_ctx[((size_t)(row0 + 8) * BATCH + b) * EMB + col] = hi;
    }
}

// ---------------------------------------------------------------------------
extern "C" void kernel_launch(void* const* d_in, const int* in_sizes, int n_in,
                              void* d_out, int out_size)
{
    const float* query = (const float*)d_in[0];
    const float* w_in  = (const float*)d_in[1];
    const float* b_in  = (const float*)d_in[2];
    const float* w_out = (const float*)d_in[3];
    const float* b_out = (const float*)d_in[4];
    float* out = (float*)d_out;

    float *lin_ptr, *ctx_ptr;
    cudaGetSymbolAddress((void**)&lin_ptr, g_lin);
    cudaGetSymbolAddress((void**)&ctx_ptr, g_ctx);

    const int smem = (128 * QS_STR + 64 * KS_STR + 64 * VS_STR + 128 * PS_STR)
                     * (int)sizeof(unsigned);   // 105,472 B
    cudaFuncSetAttribute(attn_mma_kernel,
                         cudaFuncAttributeMaxDynamicSharedMemorySize, smem);

    // 1) lin = query @ W_in^T + b_in   [8192 x 3072]  (tf32 MMA)
    gemm_tf32_nt_bias<<<dim3(E3 / 128, MROWS / 128), 256>>>(
        query, w_in, b_in, lin_ptr, MROWS, E3, EMB);

    // 2) flash attention -> g_ctx  (tf32 MMA QK^T and PV)
    attn_mma_kernel<<<dim3(S_LEN / 128, BATCH * HEADS), 256, smem>>>();

    // 3) out = ctx @ W_out^T + b_out   [8192 x 1024]  (tf32 MMA)
    gemm_tf32_nt_bias<<<dim3(EMB / 128, MROWS / 128), 256>>>(
        ctx_ptr, w_out, b_out, out, MROWS, EMB, EMB);
}